// round 15
// baseline (speedup 1.0000x reference)
#include <cuda_runtime.h>
#include <cuda_fp16.h>
#include <math.h>
#include <stdint.h>

#define B 64
#define R 196
#define L 512
#define K 768

// ---------------------------------------------------------------------------
// Scratch (no cudaMalloc allowed).
// ---------------------------------------------------------------------------
__device__ float g_c[B * R];                             // 1 + tanh(image proj)
__device__ float g_q[B * L];                             // tanh(seq proj)
__device__ float g_wc[B * L];                            // compacted (w - M)
__device__ unsigned short g_S[((size_t)B * R + 64) * L]; // compacted softmax, fp16
__device__ unsigned short g_Eh[(size_t)B * L * K];       // seq_emb in fp16
__device__ int g_pos[B * L];                             // compacted column index
__device__ int g_cnt[B * 2];                             // [2b]=cnt, [2b+1]=cntp

__device__ __forceinline__ uint32_t pack_f2h(float a, float b) {
    return (uint32_t)__half_as_ushort(__float2half_rn(a)) |
           ((uint32_t)__half_as_ushort(__float2half_rn(b)) << 16);
}
__device__ __forceinline__ uint32_t smem_u32(const void* p) {
    uint32_t a;
    asm("{ .reg .u64 t; cvta.to.shared.u64 t, %1; cvt.u32.u64 %0, t; }"
        : "=r"(a) : "l"(p));
    return a;
}
#define CP_ASYNC16(dst, src) \
    asm volatile("cp.async.cg.shared.global [%0], [%1], 16;" :: "r"(dst), "l"(src))
#define CP_COMMIT() asm volatile("cp.async.commit_group;" ::: "memory")
#define CP_WAIT0()  asm volatile("cp.async.wait_group 0;" ::: "memory")

// ---------------------------------------------------------------------------
// Kernel 1 (prep1): fused p/q projections + fp16 transcode of seq_emb.
// ---------------------------------------------------------------------------
__global__ void k_prep1(const float* __restrict__ img, const float* __restrict__ iW,
                        const float* __restrict__ ib, const float* __restrict__ seq,
                        const float* __restrict__ sW, const float* __restrict__ sb2) {
    int gid = (blockIdx.x * blockDim.x + threadIdx.x) >> 5;
    int lane = threadIdx.x & 31;
    if (gid < B * R) {
        const float4* row = (const float4*)(img + (size_t)gid * L);
        const float4* W4 = (const float4*)iW;
        float s = 0.f;
#pragma unroll
        for (int i = 0; i < L / 128; i++) {
            float4 a = row[lane + 32 * i], w = W4[lane + 32 * i];
            s += a.x * w.x + a.y * w.y + a.z * w.z + a.w * w.w;
        }
#pragma unroll
        for (int o = 16; o; o >>= 1) s += __shfl_xor_sync(0xffffffffu, s, o);
        if (lane == 0) g_c[gid] = 1.0f + tanhf(s + ib[0]);
    } else {
        int rq = gid - B * R;
        const float4* row = (const float4*)(seq + (size_t)rq * K);
        const float4* W4 = (const float4*)sW;
        uint2* eh = (uint2*)(g_Eh + (size_t)rq * K);
        float s = 0.f;
#pragma unroll
        for (int i = 0; i < K / 128; i++) {
            float4 a = row[lane + 32 * i], w = W4[lane + 32 * i];
            s += a.x * w.x + a.y * w.y + a.z * w.z + a.w * w.w;
            eh[lane + 32 * i] = make_uint2(pack_f2h(a.x, a.y), pack_f2h(a.z, a.w));
        }
#pragma unroll
        for (int o = 16; o; o >>= 1) s += __shfl_xor_sync(0xffffffffu, s, o);
        if (lane == 0) g_q[rq] = tanhf(s + sb2[0]);
    }
}

// ---------------------------------------------------------------------------
// Kernel 2 (prep2a): per-batch w = q@V, ballot compaction (monolithic).
// ---------------------------------------------------------------------------
__global__ __launch_bounds__(512) void k_prep2a(const int* __restrict__ mask,
                                                const float* __restrict__ V) {
    const int b = blockIdx.x;
    const int t = threadIdx.x;
    const int wid = t >> 5;
    const int lane = t & 31;
    __shared__ float qs[L];
    __shared__ float ws[L];
    __shared__ int posArr[L];
    __shared__ int warpcnt[16];
    __shared__ int warpoff[17];
    __shared__ float warpmax[16];
    __shared__ float Msh;

    qs[t] = g_q[b * L + t];
    int mt = mask[b * L + t];
    uint32_t bal = __ballot_sync(0xffffffffu, mt != 0);
    int inwarp = __popc(bal & ((1u << lane) - 1u));
    if (lane == 0) warpcnt[wid] = __popc(bal);
    __syncthreads();
    if (t == 0) {
        int s = 0;
#pragma unroll
        for (int i = 0; i < 16; i++) { warpoff[i] = s; s += warpcnt[i]; }
        warpoff[16] = s;
    }
    __syncthreads();
    const int cnt = warpoff[16];
    const int cntp = (cnt + 31) & ~31;

    float acc = 0.f;
#pragma unroll 8
    for (int l = 0; l < L; l++) acc += qs[l] * V[l * L + t];
    ws[t] = acc;

    float mm = mt ? acc : -INFINITY;
#pragma unroll
    for (int o = 16; o; o >>= 1) mm = fmaxf(mm, __shfl_xor_sync(0xffffffffu, mm, o));
    if (lane == 0) warpmax[wid] = mm;
    if (mt) posArr[warpoff[wid] + inwarp] = t;
    if (t >= cnt && t < cntp) posArr[t] = 0;
    __syncthreads();
    if (t == 0) {
        float M = -INFINITY;
#pragma unroll
        for (int i = 0; i < 16; i++) M = fmaxf(M, warpmax[i]);
        Msh = M;
        g_cnt[2 * b] = cnt;
        g_cnt[2 * b + 1] = cntp;
    }
    __syncthreads();
    if (t < cntp) {
        g_wc[b * L + t] = (t < cnt) ? ws[posArr[t]] - Msh : 0.f;
        g_pos[b * L + t] = posArr[t];
    }
}

// ---------------------------------------------------------------------------
// Kernel 3 (prep2b): softmax rows -> g_S fp16, packed half2 stores.
// ---------------------------------------------------------------------------
__global__ __launch_bounds__(256) void k_prep2b() {
    const int b = blockIdx.x;
    const int t = threadIdx.x;
    const int wid = t >> 5;
    const int lane = t & 31;
    __shared__ float wcs[L];
    __shared__ int cntS[2];
    if (t < 2) cntS[t] = g_cnt[2 * b + t];
    __syncthreads();
    const int cnt = cntS[0];
    const int cntp = cntS[1];
    for (int j = t; j < cntp; j += 256) wcs[j] = g_wc[b * L + j];
    __syncthreads();

    const int r = blockIdx.y * 8 + wid;
    if (r >= R) return;
    const float c = g_c[b * R + r];
    float e[16];
    float z = 0.f;
#pragma unroll
    for (int i = 0; i < 8; i++) {
        int j = 2 * (lane + 32 * i);
        float e0 = 0.f, e1 = 0.f;
        if (j < cnt)     { e0 = __expf(c * wcs[j]);     z += e0; }
        if (j + 1 < cnt) { e1 = __expf(c * wcs[j + 1]); z += e1; }
        e[2 * i] = e0;
        e[2 * i + 1] = e1;
    }
#pragma unroll
    for (int o = 16; o; o >>= 1) z += __shfl_xor_sync(0xffffffffu, z, o);
    const float inv = 1.0f / (z * 27.712812921102035f);   // fold 1/sqrt(768)
    uint32_t* Srow32 = (uint32_t*)(g_S + ((size_t)(b * R + r)) * L);
    const int c2 = cntp >> 1;
#pragma unroll
    for (int i = 0; i < 8; i++) {
        int j2 = lane + 32 * i;
        if (j2 < c2)
            Srow32[j2] = pack_f2h(e[2 * i] * inv, e[2 * i + 1] * inv);
    }
}

// ---------------------------------------------------------------------------
// Kernel 4: out[b] = S_compact[b] @ gather(Eh[b], pos[b]).
// RETILED: BM=128, BN=64; 8 warps = 4(M) x 2(N), warp tile 32x32.
// acc 32 regs/thread -> 3 CTAs/SM. cp.async fills, ldmatrix frags.
// ---------------------------------------------------------------------------
#define BM 128
#define BN 64
#define BK 32
#define APITCH 40    // halves; row stride 80 B
#define BPITCH 72    // halves; row stride 144 B (4-bank offset: LDSM-clean)
#define ABUF (BM * APITCH * 2)  // 10240 B
#define BBUF (BK * BPITCH * 2)  // 4608 B

__global__ __launch_bounds__(256, 3) void k_gemm_f16(float* __restrict__ out) {
    const int b = blockIdx.z;
    const int m0 = blockIdx.y * BM;
    const int n0 = blockIdx.x * BN;
    const unsigned short* Sb = g_S + (size_t)b * R * L;
    const unsigned short* Eb = g_Eh + (size_t)b * L * K + n0;
    float* Ob = out + (size_t)b * R * K;

    __shared__ __align__(16) unsigned short As[2][BM * APITCH];
    __shared__ __align__(16) unsigned short Bs[2][BK * BPITCH];
    __shared__ int posS[L];

    const int t = threadIdx.x;
    const int wid = t >> 5;
    const int lane = t & 31;
    const int warp_m = (wid & 3) * 32;
    const int warp_n = (wid >> 2) * 32;
    const int lq = lane >> 2;
    const int lr = lane & 3;

    const int nit = g_cnt[2 * b + 1] >> 5;   // dynamic K-iterations

    const int a_row0 = t >> 2, a_c8 = t & 3;   // A: 2 x 16B/thread (rows +64)
    const int b_kr0 = t >> 3, b_n8 = t & 7;    // B: 1 x 16B/thread (32 rows x 8 segs)

    const int l8 = lane & 7;
    const int sel = lane >> 3;
    const int selm = sel & 1;
    const int selk = sel >> 1;
    const uint32_t sA = smem_u32(&As[0][0]);
    const uint32_t sB = smem_u32(&Bs[0][0]);
    const uint32_t aBase = sA + (uint32_t)((warp_m + selm * 8 + l8) * 80 + selk * 16);
    const uint32_t bBase = sB + (uint32_t)((selm * 8 + l8) * 144 + (warp_n + selk * 8) * 2);
    const uint32_t aSt = sA + (uint32_t)(a_row0 * 80 + a_c8 * 16);
    const uint32_t bSt = sB + (uint32_t)(b_kr0 * 144 + b_n8 * 16);

    posS[t] = g_pos[b * L + t];
    posS[t + 256] = g_pos[b * L + t + 256];
    __syncthreads();

    float acc[2][4][4];
#pragma unroll
    for (int i = 0; i < 2; i++)
#pragma unroll
        for (int j = 0; j < 4; j++)
#pragma unroll
            for (int k2 = 0; k2 < 4; k2++) acc[i][j][k2] = 0.f;

    // tile 0 via cp.async -> buffer 0
#pragma unroll
    for (int i = 0; i < 2; i++)
        CP_ASYNC16(aSt + (uint32_t)(i * 64 * 80),
                   &Sb[(size_t)(m0 + a_row0 + i * 64) * L + a_c8 * 8]);
    CP_ASYNC16(bSt, &Eb[(size_t)posS[b_kr0] * K + b_n8 * 8]);
    CP_COMMIT();
    CP_WAIT0();
    __syncthreads();

    int buf = 0;
    for (int it = 0; it < nit; it++) {
        // issue next tile's cp.async into the other buffer
        if (it + 1 < nit) {
            const int k0 = (it + 1) * BK;
            const uint32_t aD = aSt + (uint32_t)((buf ^ 1) * ABUF);
            const uint32_t bD = bSt + (uint32_t)((buf ^ 1) * BBUF);
#pragma unroll
            for (int i = 0; i < 2; i++)
                CP_ASYNC16(aD + (uint32_t)(i * 64 * 80),
                           &Sb[(size_t)(m0 + a_row0 + i * 64) * L + k0 + a_c8 * 8]);
            CP_ASYNC16(bD, &Eb[(size_t)posS[k0 + b_kr0] * K + b_n8 * 8]);
            CP_COMMIT();
        }

        // mma burst on buf
        const uint32_t aB = aBase + (uint32_t)buf * ABUF;
        const uint32_t bB = bBase + (uint32_t)buf * BBUF;
#pragma unroll
        for (int ks = 0; ks < 2; ks++) {
            uint32_t af[2][4];
#pragma unroll
            for (int mi = 0; mi < 2; mi++) {
                uint32_t addr = aB + (uint32_t)(mi * 16 * 80 + ks * 32);
                asm volatile(
                    "ldmatrix.sync.aligned.m8n8.x4.shared.b16 {%0,%1,%2,%3}, [%4];"
                    : "=r"(af[mi][0]), "=r"(af[mi][1]), "=r"(af[mi][2]), "=r"(af[mi][3])
                    : "r"(addr));
            }
            uint32_t bf[4][2];
#pragma unroll
            for (int g = 0; g < 2; g++) {
                uint32_t addr = bB + (uint32_t)(ks * 16 * 144 + g * 32);
                asm volatile(
                    "ldmatrix.sync.aligned.m8n8.x4.trans.shared.b16 {%0,%1,%2,%3}, [%4];"
                    : "=r"(bf[2 * g][0]), "=r"(bf[2 * g][1]),
                      "=r"(bf[2 * g + 1][0]), "=r"(bf[2 * g + 1][1])
                    : "r"(addr));
            }
#pragma unroll
            for (int mi = 0; mi < 2; mi++)
#pragma unroll
                for (int ni = 0; ni < 4; ni++) {
                    asm volatile(
                        "mma.sync.aligned.m16n8k16.row.col.f32.f16.f16.f32 "
                        "{%0,%1,%2,%3}, {%4,%5,%6,%7}, {%8,%9}, {%0,%1,%2,%3};"
                        : "+f"(acc[mi][ni][0]), "+f"(acc[mi][ni][1]),
                          "+f"(acc[mi][ni][2]), "+f"(acc[mi][ni][3])
                        : "r"(af[mi][0]), "r"(af[mi][1]), "r"(af[mi][2]), "r"(af[mi][3]),
                          "r"(bf[ni][0]), "r"(bf[ni][1]));
                }
        }

        if (it + 1 < nit) CP_WAIT0();
        __syncthreads();
        buf ^= 1;
    }

    // Epilogue
#pragma unroll
    for (int mi = 0; mi < 2; mi++) {
#pragma unroll
        for (int ni = 0; ni < 4; ni++) {
            int gn = n0 + warp_n + ni * 8 + 2 * lr;
            int gm0 = m0 + warp_m + mi * 16 + lq;
            if (gm0 < R) {
                float2 v = make_float2(acc[mi][ni][0], acc[mi][ni][1]);
                *(float2*)&Ob[(size_t)gm0 * K + gn] = v;
            }
            int gm1 = gm0 + 8;
            if (gm1 < R) {
                float2 v = make_float2(acc[mi][ni][2], acc[mi][ni][3]);
                *(float2*)&Ob[(size_t)gm1 * K + gn] = v;
            }
        }
    }
}

// ---------------------------------------------------------------------------
extern "C" void kernel_launch(void* const* d_in, const int* in_sizes, int n_in,
                              void* d_out, int out_size) {
    const float* image_emb = (const float*)d_in[0]; // [B,R,L]
    const float* seq_emb   = (const float*)d_in[1]; // [B,L,K]
    const int*   mask      = (const int*)d_in[2];   // [B,L]
    const float* image_W   = (const float*)d_in[3]; // [L,1]
    const float* image_b   = (const float*)d_in[4]; // [1]
    const float* seq_W     = (const float*)d_in[5]; // [K,1]
    const float* seq_b     = (const float*)d_in[6]; // [1]
    const float* V_weight  = (const float*)d_in[7]; // [L,L]
    float* out = (float*)d_out;                     // [B,R,K]

    k_prep1<<<(B * R + B * L) / 8, 256>>>(image_emb, image_W, image_b,
                                          seq_emb, seq_W, seq_b);
    k_prep2a<<<B, 512>>>(mask, V_weight);
    k_prep2b<<<dim3(B, 25), 256>>>();
    k_gemm_f16<<<dim3(K / BN, (R + BM - 1) / BM, B), 256>>>(out);
}

// round 16
// speedup vs baseline: 1.0769x; 1.0769x over previous
#include <cuda_runtime.h>
#include <cuda_fp16.h>
#include <math.h>
#include <stdint.h>

#define B 64
#define R 196
#define L 512
#define K 768

// ---------------------------------------------------------------------------
// Scratch (no cudaMalloc allowed).
// ---------------------------------------------------------------------------
__device__ float g_c[B * R];                             // 1 + tanh(image proj)
__device__ float g_q[B * L];                             // tanh(seq proj)
__device__ float g_wc[B * L];                            // compacted (w - M)
__device__ unsigned short g_S[((size_t)B * R + 64) * L]; // compacted softmax, fp16
__device__ unsigned short g_Eh[(size_t)B * L * K];       // seq_emb in fp16
__device__ int g_pos[B * L];                             // compacted column index
__device__ int g_cnt[B * 2];                             // [2b]=cnt, [2b+1]=cntp

__device__ __forceinline__ uint32_t pack_f2h(float a, float b) {
    return (uint32_t)__half_as_ushort(__float2half_rn(a)) |
           ((uint32_t)__half_as_ushort(__float2half_rn(b)) << 16);
}
__device__ __forceinline__ uint32_t smem_u32(const void* p) {
    uint32_t a;
    asm("{ .reg .u64 t; cvta.to.shared.u64 t, %1; cvt.u32.u64 %0, t; }"
        : "=r"(a) : "l"(p));
    return a;
}
#define CP_ASYNC16(dst, src) \
    asm volatile("cp.async.cg.shared.global [%0], [%1], 16;" :: "r"(dst), "l"(src))
#define CP_COMMIT() asm volatile("cp.async.commit_group;" ::: "memory")
#define CP_WAIT0()  asm volatile("cp.async.wait_group 0;" ::: "memory")
#define CP_WAIT1()  asm volatile("cp.async.wait_group 1;" ::: "memory")

// ---------------------------------------------------------------------------
// Kernel 1 (prep1): fused p/q projections + fp16 transcode of seq_emb.
// ---------------------------------------------------------------------------
__global__ void k_prep1(const float* __restrict__ img, const float* __restrict__ iW,
                        const float* __restrict__ ib, const float* __restrict__ seq,
                        const float* __restrict__ sW, const float* __restrict__ sb2) {
    int gid = (blockIdx.x * blockDim.x + threadIdx.x) >> 5;
    int lane = threadIdx.x & 31;
    if (gid < B * R) {
        const float4* row = (const float4*)(img + (size_t)gid * L);
        const float4* W4 = (const float4*)iW;
        float s = 0.f;
#pragma unroll
        for (int i = 0; i < L / 128; i++) {
            float4 a = row[lane + 32 * i], w = W4[lane + 32 * i];
            s += a.x * w.x + a.y * w.y + a.z * w.z + a.w * w.w;
        }
#pragma unroll
        for (int o = 16; o; o >>= 1) s += __shfl_xor_sync(0xffffffffu, s, o);
        if (lane == 0) g_c[gid] = 1.0f + tanhf(s + ib[0]);
    } else {
        int rq = gid - B * R;
        const float4* row = (const float4*)(seq + (size_t)rq * K);
        const float4* W4 = (const float4*)sW;
        uint2* eh = (uint2*)(g_Eh + (size_t)rq * K);
        float s = 0.f;
#pragma unroll
        for (int i = 0; i < K / 128; i++) {
            float4 a = row[lane + 32 * i], w = W4[lane + 32 * i];
            s += a.x * w.x + a.y * w.y + a.z * w.z + a.w * w.w;
            eh[lane + 32 * i] = make_uint2(pack_f2h(a.x, a.y), pack_f2h(a.z, a.w));
        }
#pragma unroll
        for (int o = 16; o; o >>= 1) s += __shfl_xor_sync(0xffffffffu, s, o);
        if (lane == 0) g_q[rq] = tanhf(s + sb2[0]);
    }
}

// ---------------------------------------------------------------------------
// Kernel 2 (prep2a): per-batch w = q@V, ballot compaction (monolithic).
// ---------------------------------------------------------------------------
__global__ __launch_bounds__(512) void k_prep2a(const int* __restrict__ mask,
                                                const float* __restrict__ V) {
    const int b = blockIdx.x;
    const int t = threadIdx.x;
    const int wid = t >> 5;
    const int lane = t & 31;
    __shared__ float qs[L];
    __shared__ float ws[L];
    __shared__ int posArr[L];
    __shared__ int warpcnt[16];
    __shared__ int warpoff[17];
    __shared__ float warpmax[16];
    __shared__ float Msh;

    qs[t] = g_q[b * L + t];
    int mt = mask[b * L + t];
    uint32_t bal = __ballot_sync(0xffffffffu, mt != 0);
    int inwarp = __popc(bal & ((1u << lane) - 1u));
    if (lane == 0) warpcnt[wid] = __popc(bal);
    __syncthreads();
    if (t == 0) {
        int s = 0;
#pragma unroll
        for (int i = 0; i < 16; i++) { warpoff[i] = s; s += warpcnt[i]; }
        warpoff[16] = s;
    }
    __syncthreads();
    const int cnt = warpoff[16];
    const int cntp = (cnt + 31) & ~31;

    float acc = 0.f;
#pragma unroll 8
    for (int l = 0; l < L; l++) acc += qs[l] * V[l * L + t];
    ws[t] = acc;

    float mm = mt ? acc : -INFINITY;
#pragma unroll
    for (int o = 16; o; o >>= 1) mm = fmaxf(mm, __shfl_xor_sync(0xffffffffu, mm, o));
    if (lane == 0) warpmax[wid] = mm;
    if (mt) posArr[warpoff[wid] + inwarp] = t;
    if (t >= cnt && t < cntp) posArr[t] = 0;
    __syncthreads();
    if (t == 0) {
        float M = -INFINITY;
#pragma unroll
        for (int i = 0; i < 16; i++) M = fmaxf(M, warpmax[i]);
        Msh = M;
        g_cnt[2 * b] = cnt;
        g_cnt[2 * b + 1] = cntp;
    }
    __syncthreads();
    if (t < cntp) {
        g_wc[b * L + t] = (t < cnt) ? ws[posArr[t]] - Msh : 0.f;
        g_pos[b * L + t] = posArr[t];
    }
}

// ---------------------------------------------------------------------------
// Kernel 3 (prep2b): softmax rows -> g_S fp16, packed half2 stores.
// ---------------------------------------------------------------------------
__global__ __launch_bounds__(256) void k_prep2b() {
    const int b = blockIdx.x;
    const int t = threadIdx.x;
    const int wid = t >> 5;
    const int lane = t & 31;
    __shared__ float wcs[L];
    __shared__ int cntS[2];
    if (t < 2) cntS[t] = g_cnt[2 * b + t];
    __syncthreads();
    const int cnt = cntS[0];
    const int cntp = cntS[1];
    for (int j = t; j < cntp; j += 256) wcs[j] = g_wc[b * L + j];
    __syncthreads();

    const int r = blockIdx.y * 8 + wid;
    if (r >= R) return;
    const float c = g_c[b * R + r];
    float e[16];
    float z = 0.f;
#pragma unroll
    for (int i = 0; i < 8; i++) {
        int j = 2 * (lane + 32 * i);
        float e0 = 0.f, e1 = 0.f;
        if (j < cnt)     { e0 = __expf(c * wcs[j]);     z += e0; }
        if (j + 1 < cnt) { e1 = __expf(c * wcs[j + 1]); z += e1; }
        e[2 * i] = e0;
        e[2 * i + 1] = e1;
    }
#pragma unroll
    for (int o = 16; o; o >>= 1) z += __shfl_xor_sync(0xffffffffu, z, o);
    const float inv = 1.0f / (z * 27.712812921102035f);   // fold 1/sqrt(768)
    uint32_t* Srow32 = (uint32_t*)(g_S + ((size_t)(b * R + r)) * L);
    const int c2 = cntp >> 1;
#pragma unroll
    for (int i = 0; i < 8; i++) {
        int j2 = lane + 32 * i;
        if (j2 < c2)
            Srow32[j2] = pack_f2h(e[2 * i] * inv, e[2 * i + 1] * inv);
    }
}

// ---------------------------------------------------------------------------
// Kernel 4: out[b] = S_compact[b] @ gather(Eh[b], pos[b]).
// BM=128, BN=128 (best tiling), 3-STAGE cp.async pipeline, prefetch dist 2,
// wait_group 1 per iteration -> gmem latency fully hidden. Dynamic smem.
// ---------------------------------------------------------------------------
#define BM 128
#define BN 128
#define BK 32
#define APITCH 40    // halves; row stride 80 B
#define BPITCH 136   // halves; row stride 272 B
#define ABUF (BM * APITCH * 2)  // 10240 B per stage
#define BBUF (BK * BPITCH * 2)  // 8704 B per stage
#define STAGES 3
#define SMEM_GEMM (STAGES * (ABUF + BBUF))   // 56832 B

__global__ __launch_bounds__(256, 2) void k_gemm_f16(float* __restrict__ out) {
    const int b = blockIdx.z;
    const int m0 = blockIdx.y * BM;
    const int n0 = blockIdx.x * BN;
    const unsigned short* Sb = g_S + (size_t)b * R * L;
    const unsigned short* Eb = g_Eh + (size_t)b * L * K + n0;
    float* Ob = out + (size_t)b * R * K;

    extern __shared__ __align__(16) unsigned char smem[];
    __shared__ int posS[L];

    const int t = threadIdx.x;
    const int wid = t >> 5;
    const int lane = t & 31;
    const int warp_m = (wid & 3) * 32;
    const int warp_n = (wid >> 2) * 64;
    const int lq = lane >> 2;
    const int lr = lane & 3;

    const int nit = g_cnt[2 * b + 1] >> 5;   // dynamic K-iterations (~8)

    const int a_row0 = t >> 2, a_c8 = t & 3;   // A: 2 x 16B/thread (rows +64)
    const int b_kr0 = t >> 4, b_n8 = t & 15;   // B: 2 x 16B/thread (rows +16)

    const int l8 = lane & 7;
    const int sel = lane >> 3;
    const int selm = sel & 1;
    const int selk = sel >> 1;
    const uint32_t sA = smem_u32(smem);                     // 3 A stages
    const uint32_t sB = sA + STAGES * ABUF;                  // 3 B stages
    const uint32_t aBase = sA + (uint32_t)((warp_m + selm * 8 + l8) * 80 + selk * 16);
    const uint32_t bBase = sB + (uint32_t)((selm * 8 + l8) * 272 + (warp_n + selk * 8) * 2);
    const uint32_t aSt = sA + (uint32_t)(a_row0 * 80 + a_c8 * 16);
    const uint32_t bSt = sB + (uint32_t)(b_kr0 * 272 + b_n8 * 16);

    posS[t] = g_pos[b * L + t];
    posS[t + 256] = g_pos[b * L + t + 256];
    __syncthreads();

    float acc[2][8][4];
#pragma unroll
    for (int i = 0; i < 2; i++)
#pragma unroll
        for (int j = 0; j < 8; j++)
#pragma unroll
            for (int k2 = 0; k2 < 4; k2++) acc[i][j][k2] = 0.f;

    // ---- prologue: issue tiles 0 and 1 into stages 0 and 1 ----
    {
#pragma unroll
        for (int i = 0; i < 2; i++)
            CP_ASYNC16(aSt + (uint32_t)(i * 64 * 80),
                       &Sb[(size_t)(m0 + a_row0 + i * 64) * L + a_c8 * 8]);
#pragma unroll
        for (int i = 0; i < 2; i++)
            CP_ASYNC16(bSt + (uint32_t)(i * 16 * 272),
                       &Eb[(size_t)posS[b_kr0 + i * 16] * K + b_n8 * 8]);
        CP_COMMIT();
    }
    if (nit > 1) {
        const uint32_t aD = aSt + ABUF;
        const uint32_t bD = bSt + BBUF;
#pragma unroll
        for (int i = 0; i < 2; i++)
            CP_ASYNC16(aD + (uint32_t)(i * 64 * 80),
                       &Sb[(size_t)(m0 + a_row0 + i * 64) * L + BK + a_c8 * 8]);
#pragma unroll
        for (int i = 0; i < 2; i++)
            CP_ASYNC16(bD + (uint32_t)(i * 16 * 272),
                       &Eb[(size_t)posS[BK + b_kr0 + i * 16] * K + b_n8 * 8]);
        CP_COMMIT();
        CP_WAIT1();              // tile 0 complete
    } else {
        CP_WAIT0();
    }
    __syncthreads();

    int buf = 0;
    for (int it = 0; it < nit; it++) {
        // mma burst on stage buf
        const uint32_t aB = aBase + (uint32_t)buf * ABUF;
        const uint32_t bB = bBase + (uint32_t)buf * BBUF;
#pragma unroll
        for (int ks = 0; ks < 2; ks++) {
            uint32_t af[2][4];
#pragma unroll
            for (int mi = 0; mi < 2; mi++) {
                uint32_t addr = aB + (uint32_t)(mi * 16 * 80 + ks * 32);
                asm volatile(
                    "ldmatrix.sync.aligned.m8n8.x4.shared.b16 {%0,%1,%2,%3}, [%4];"
                    : "=r"(af[mi][0]), "=r"(af[mi][1]), "=r"(af[mi][2]), "=r"(af[mi][3])
                    : "r"(addr));
            }
            uint32_t bf[8][2];
#pragma unroll
            for (int g = 0; g < 4; g++) {
                uint32_t addr = bB + (uint32_t)(ks * 16 * 272 + g * 32);
                asm volatile(
                    "ldmatrix.sync.aligned.m8n8.x4.trans.shared.b16 {%0,%1,%2,%3}, [%4];"
                    : "=r"(bf[2 * g][0]), "=r"(bf[2 * g][1]),
                      "=r"(bf[2 * g + 1][0]), "=r"(bf[2 * g + 1][1])
                    : "r"(addr));
            }
#pragma unroll
            for (int mi = 0; mi < 2; mi++)
#pragma unroll
                for (int ni = 0; ni < 8; ni++) {
                    asm volatile(
                        "mma.sync.aligned.m16n8k16.row.col.f32.f16.f16.f32 "
                        "{%0,%1,%2,%3}, {%4,%5,%6,%7}, {%8,%9}, {%0,%1,%2,%3};"
                        : "+f"(acc[mi][ni][0]), "+f"(acc[mi][ni][1]),
                          "+f"(acc[mi][ni][2]), "+f"(acc[mi][ni][3])
                        : "r"(af[mi][0]), "r"(af[mi][1]), "r"(af[mi][2]), "r"(af[mi][3]),
                          "r"(bf[ni][0]), "r"(bf[ni][1]));
                }
        }

        // issue tile it+2 into the stage being vacated next, then wait tile it+1
        if (it + 2 < nit) {
            int is = buf + 2; if (is >= STAGES) is -= STAGES;
            const int k0 = (it + 2) * BK;
            const uint32_t aD = aSt + (uint32_t)is * ABUF;
            const uint32_t bD = bSt + (uint32_t)is * BBUF;
#pragma unroll
            for (int i = 0; i < 2; i++)
                CP_ASYNC16(aD + (uint32_t)(i * 64 * 80),
                           &Sb[(size_t)(m0 + a_row0 + i * 64) * L + k0 + a_c8 * 8]);
#pragma unroll
            for (int i = 0; i < 2; i++)
                CP_ASYNC16(bD + (uint32_t)(i * 16 * 272),
                           &Eb[(size_t)posS[k0 + b_kr0 + i * 16] * K + b_n8 * 8]);
            CP_COMMIT();
            CP_WAIT1();          // tile it+1 complete (distance-2 pipeline)
        } else if (it + 1 < nit) {
            CP_WAIT0();          // drain the last in-flight tile
        }
        __syncthreads();
        if (++buf == STAGES) buf = 0;
    }

    // Epilogue
#pragma unroll
    for (int mi = 0; mi < 2; mi++) {
#pragma unroll
        for (int ni = 0; ni < 8; ni++) {
            int gn = n0 + warp_n + ni * 8 + 2 * lr;
            int gm0 = m0 + warp_m + mi * 16 + lq;
            if (gm0 < R) {
                float2 v = make_float2(acc[mi][ni][0], acc[mi][ni][1]);
                *(float2*)&Ob[(size_t)gm0 * K + gn] = v;
            }
            int gm1 = gm0 + 8;
            if (gm1 < R) {
                float2 v = make_float2(acc[mi][ni][2], acc[mi][ni][3]);
                *(float2*)&Ob[(size_t)gm1 * K + gn] = v;
            }
        }
    }
}

// ---------------------------------------------------------------------------
extern "C" void kernel_launch(void* const* d_in, const int* in_sizes, int n_in,
                              void* d_out, int out_size) {
    const float* image_emb = (const float*)d_in[0]; // [B,R,L]
    const float* seq_emb   = (const float*)d_in[1]; // [B,L,K]
    const int*   mask      = (const int*)d_in[2];   // [B,L]
    const float* image_W   = (const float*)d_in[3]; // [L,1]
    const float* image_b   = (const float*)d_in[4]; // [1]
    const float* seq_W     = (const float*)d_in[5]; // [K,1]
    const float* seq_b     = (const float*)d_in[6]; // [1]
    const float* V_weight  = (const float*)d_in[7]; // [L,L]
    float* out = (float*)d_out;                     // [B,R,K]

    cudaFuncSetAttribute(k_gemm_f16, cudaFuncAttributeMaxDynamicSharedMemorySize,
                         SMEM_GEMM);

    k_prep1<<<(B * R + B * L) / 8, 256>>>(image_emb, image_W, image_b,
                                          seq_emb, seq_W, seq_b);
    k_prep2a<<<B, 512>>>(mask, V_weight);
    k_prep2b<<<dim3(B, 25), 256>>>();
    k_gemm_f16<<<dim3(K / BN, (R + BM - 1) / BM, B), 256, SMEM_GEMM>>>(out);
}

// round 17
// speedup vs baseline: 1.1726x; 1.0889x over previous
#include <cuda_runtime.h>
#include <cuda_fp16.h>
#include <math.h>
#include <stdint.h>

#define B 64
#define R 196
#define L 512
#define K 768

// ---------------------------------------------------------------------------
// Scratch (no cudaMalloc allowed).
// ---------------------------------------------------------------------------
__device__ float g_c[B * R];                             // 1 + tanh(image proj)
__device__ float g_q[B * L];                             // tanh(seq proj)
__device__ unsigned short g_S[((size_t)B * R + 64) * L]; // compacted softmax, fp16
__device__ unsigned short g_Eh[(size_t)B * L * K];       // seq_emb fp16 (unmasked rows)
__device__ int g_pos[B * L];                             // compacted column index
__device__ int g_cnt[B * 2];                             // [2b]=cnt, [2b+1]=cntp

__device__ __forceinline__ uint32_t pack_f2h(float a, float b) {
    return (uint32_t)__half_as_ushort(__float2half_rn(a)) |
           ((uint32_t)__half_as_ushort(__float2half_rn(b)) << 16);
}
__device__ __forceinline__ uint32_t smem_u32(const void* p) {
    uint32_t a;
    asm("{ .reg .u64 t; cvta.to.shared.u64 t, %1; cvt.u32.u64 %0, t; }"
        : "=r"(a) : "l"(p));
    return a;
}
#define CP_ASYNC16(dst, src) \
    asm volatile("cp.async.cg.shared.global [%0], [%1], 16;" :: "r"(dst), "l"(src))
#define CP_COMMIT() asm volatile("cp.async.commit_group;" ::: "memory")
#define CP_WAIT0()  asm volatile("cp.async.wait_group 0;" ::: "memory")
#define CP_WAIT1()  asm volatile("cp.async.wait_group 1;" ::: "memory")

// ---------------------------------------------------------------------------
// Kernel 1 (prep1): fused p/q projections + fp16 transcode of UNMASKED E rows.
// ---------------------------------------------------------------------------
__global__ void k_prep1(const float* __restrict__ img, const float* __restrict__ iW,
                        const float* __restrict__ ib, const float* __restrict__ seq,
                        const float* __restrict__ sW, const float* __restrict__ sb2,
                        const int* __restrict__ mask) {
    int gid = (blockIdx.x * blockDim.x + threadIdx.x) >> 5;
    int lane = threadIdx.x & 31;
    if (gid < B * R) {
        const float4* row = (const float4*)(img + (size_t)gid * L);
        const float4* W4 = (const float4*)iW;
        float s = 0.f;
#pragma unroll
        for (int i = 0; i < L / 128; i++) {
            float4 a = row[lane + 32 * i], w = W4[lane + 32 * i];
            s += a.x * w.x + a.y * w.y + a.z * w.z + a.w * w.w;
        }
#pragma unroll
        for (int o = 16; o; o >>= 1) s += __shfl_xor_sync(0xffffffffu, s, o);
        if (lane == 0) g_c[gid] = 1.0f + tanhf(s + ib[0]);
    } else {
        int rq = gid - B * R;
        const float4* row = (const float4*)(seq + (size_t)rq * K);
        const float4* W4 = (const float4*)sW;
        uint2* eh = (uint2*)(g_Eh + (size_t)rq * K);
        const int live = mask[rq];       // transcode only rows the GEMM gathers
        float s = 0.f;
#pragma unroll
        for (int i = 0; i < K / 128; i++) {
            float4 a = row[lane + 32 * i], w = W4[lane + 32 * i];
            s += a.x * w.x + a.y * w.y + a.z * w.z + a.w * w.w;
            if (live)
                eh[lane + 32 * i] = make_uint2(pack_f2h(a.x, a.y), pack_f2h(a.z, a.w));
        }
#pragma unroll
        for (int o = 16; o; o >>= 1) s += __shfl_xor_sync(0xffffffffu, s, o);
        if (lane == 0) g_q[rq] = tanhf(s + sb2[0]);
    }
}

// ---------------------------------------------------------------------------
// Kernel 2 (prep2): per-batch FUSED  w = q@V (float4 GEMV)  ->  ballot
// compaction  ->  masked softmax  ->  g_S fp16. One block per batch.
// GEMV layout: thread (g = t>>7, tj = t&127): l in [128g,128g+128),
// columns 4tj..4tj+3 via LDG.128; reduce the 4 l-chunks through smem.
// ---------------------------------------------------------------------------
__global__ __launch_bounds__(512) void k_prep2(const int* __restrict__ mask,
                                               const float* __restrict__ V) {
    const int b = blockIdx.x;
    const int t = threadIdx.x;
    const int wid = t >> 5;
    const int lane = t & 31;
    __shared__ float qs[L];
    __shared__ float red[4][L];
    __shared__ float ws[L];
    __shared__ float wcs[L];
    __shared__ int posArr[L];
    __shared__ int warpcnt[16];
    __shared__ int warpoff[17];
    __shared__ float warpmax[16];
    __shared__ float Msh;

    qs[t] = g_q[b * L + t];
    const int mt = mask[b * L + t];
    uint32_t bal = __ballot_sync(0xffffffffu, mt != 0);
    int inwarp = __popc(bal & ((1u << lane) - 1u));
    if (lane == 0) warpcnt[wid] = __popc(bal);
    __syncthreads();
    if (t == 0) {
        int s = 0;
#pragma unroll
        for (int i = 0; i < 16; i++) { warpoff[i] = s; s += warpcnt[i]; }
        warpoff[16] = s;
    }
    __syncthreads();
    const int cnt = warpoff[16];
    const int cntp = (cnt + 31) & ~31;

    // ---- GEMV: float4 loads of V ----
    {
        const int g = t >> 7;        // l-chunk 0..3
        const int tj = t & 127;      // 4-column group
        const float4* V4 = (const float4*)V;
        float4 a = make_float4(0.f, 0.f, 0.f, 0.f);
        const int l0 = g * 128;
#pragma unroll 4
        for (int l = l0; l < l0 + 128; l++) {
            float ql = qs[l];
            float4 v = V4[l * 128 + tj];
            a.x = fmaf(ql, v.x, a.x);
            a.y = fmaf(ql, v.y, a.y);
            a.z = fmaf(ql, v.z, a.z);
            a.w = fmaf(ql, v.w, a.w);
        }
        *(float4*)&red[g][4 * tj] = a;
    }
    __syncthreads();
    const float wv = red[0][t] + red[1][t] + red[2][t] + red[3][t];
    ws[t] = wv;

    // ---- masked max + compaction ----
    float mm = mt ? wv : -INFINITY;
#pragma unroll
    for (int o = 16; o; o >>= 1) mm = fmaxf(mm, __shfl_xor_sync(0xffffffffu, mm, o));
    if (lane == 0) warpmax[wid] = mm;
    if (mt) posArr[warpoff[wid] + inwarp] = t;
    if (t >= cnt && t < cntp) posArr[t] = 0;
    __syncthreads();
    if (t == 0) {
        float M = -INFINITY;
#pragma unroll
        for (int i = 0; i < 16; i++) M = fmaxf(M, warpmax[i]);
        Msh = M;
        g_cnt[2 * b] = cnt;
        g_cnt[2 * b + 1] = cntp;
    }
    __syncthreads();
    if (t < cntp) {
        wcs[t] = (t < cnt) ? ws[posArr[t]] - Msh : 0.f;
        g_pos[b * L + t] = posArr[t];
    }
    __syncthreads();

    // ---- softmax rows over compacted list (c > 0 so row max = c*M) ----
    for (int r = wid; r < R; r += 16) {
        const float c = g_c[b * R + r];
        float e[16];
        float z = 0.f;
#pragma unroll
        for (int i = 0; i < 8; i++) {
            int j = 2 * (lane + 32 * i);
            float e0 = 0.f, e1 = 0.f;
            if (j < cnt)     { e0 = __expf(c * wcs[j]);     z += e0; }
            if (j + 1 < cnt) { e1 = __expf(c * wcs[j + 1]); z += e1; }
            e[2 * i] = e0;
            e[2 * i + 1] = e1;
        }
#pragma unroll
        for (int o = 16; o; o >>= 1) z += __shfl_xor_sync(0xffffffffu, z, o);
        const float inv = 1.0f / (z * 27.712812921102035f);  // fold 1/sqrt(768)
        uint32_t* Srow32 = (uint32_t*)(g_S + ((size_t)(b * R + r)) * L);
        const int c2 = cntp >> 1;
#pragma unroll
        for (int i = 0; i < 8; i++) {
            int j2 = lane + 32 * i;
            if (j2 < c2)
                Srow32[j2] = pack_f2h(e[2 * i] * inv, e[2 * i + 1] * inv);
        }
    }
}

// ---------------------------------------------------------------------------
// Kernel 3: out[b] = S_compact[b] @ gather(Eh[b], pos[b]).
// BM=128, BN=128, 3-stage cp.async pipeline, prefetch dist 2 (as R16).
// ---------------------------------------------------------------------------
#define BM 128
#define BN 128
#define BK 32
#define APITCH 40    // halves; row stride 80 B
#define BPITCH 136   // halves; row stride 272 B
#define ABUF (BM * APITCH * 2)  // 10240 B per stage
#define BBUF (BK * BPITCH * 2)  // 8704 B per stage
#define STAGES 3
#define SMEM_GEMM (STAGES * (ABUF + BBUF))   // 56832 B

__global__ __launch_bounds__(256, 2) void k_gemm_f16(float* __restrict__ out) {
    const int b = blockIdx.z;
    const int m0 = blockIdx.y * BM;
    const int n0 = blockIdx.x * BN;
    const unsigned short* Sb = g_S + (size_t)b * R * L;
    const unsigned short* Eb = g_Eh + (size_t)b * L * K + n0;
    float* Ob = out + (size_t)b * R * K;

    extern __shared__ __align__(16) unsigned char smem[];
    __shared__ int posS[L];

    const int t = threadIdx.x;
    const int wid = t >> 5;
    const int lane = t & 31;
    const int warp_m = (wid & 3) * 32;
    const int warp_n = (wid >> 2) * 64;
    const int lq = lane >> 2;
    const int lr = lane & 3;

    const int nit = g_cnt[2 * b + 1] >> 5;   // dynamic K-iterations (~8)

    const int a_row0 = t >> 2, a_c8 = t & 3;   // A: 2 x 16B/thread (rows +64)
    const int b_kr0 = t >> 4, b_n8 = t & 15;   // B: 2 x 16B/thread (rows +16)

    const int l8 = lane & 7;
    const int sel = lane >> 3;
    const int selm = sel & 1;
    const int selk = sel >> 1;
    const uint32_t sA = smem_u32(smem);
    const uint32_t sB = sA + STAGES * ABUF;
    const uint32_t aBase = sA + (uint32_t)((warp_m + selm * 8 + l8) * 80 + selk * 16);
    const uint32_t bBase = sB + (uint32_t)((selm * 8 + l8) * 272 + (warp_n + selk * 8) * 2);
    const uint32_t aSt = sA + (uint32_t)(a_row0 * 80 + a_c8 * 16);
    const uint32_t bSt = sB + (uint32_t)(b_kr0 * 272 + b_n8 * 16);

    posS[t] = g_pos[b * L + t];
    posS[t + 256] = g_pos[b * L + t + 256];
    __syncthreads();

    float acc[2][8][4];
#pragma unroll
    for (int i = 0; i < 2; i++)
#pragma unroll
        for (int j = 0; j < 8; j++)
#pragma unroll
            for (int k2 = 0; k2 < 4; k2++) acc[i][j][k2] = 0.f;

    // ---- prologue: issue tiles 0 and 1 ----
    {
#pragma unroll
        for (int i = 0; i < 2; i++)
            CP_ASYNC16(aSt + (uint32_t)(i * 64 * 80),
                       &Sb[(size_t)(m0 + a_row0 + i * 64) * L + a_c8 * 8]);
#pragma unroll
        for (int i = 0; i < 2; i++)
            CP_ASYNC16(bSt + (uint32_t)(i * 16 * 272),
                       &Eb[(size_t)posS[b_kr0 + i * 16] * K + b_n8 * 8]);
        CP_COMMIT();
    }
    if (nit > 1) {
        const uint32_t aD = aSt + ABUF;
        const uint32_t bD = bSt + BBUF;
#pragma unroll
        for (int i = 0; i < 2; i++)
            CP_ASYNC16(aD + (uint32_t)(i * 64 * 80),
                       &Sb[(size_t)(m0 + a_row0 + i * 64) * L + BK + a_c8 * 8]);
#pragma unroll
        for (int i = 0; i < 2; i++)
            CP_ASYNC16(bD + (uint32_t)(i * 16 * 272),
                       &Eb[(size_t)posS[BK + b_kr0 + i * 16] * K + b_n8 * 8]);
        CP_COMMIT();
        CP_WAIT1();
    } else {
        CP_WAIT0();
    }
    __syncthreads();

    int buf = 0;
    for (int it = 0; it < nit; it++) {
        const uint32_t aB = aBase + (uint32_t)buf * ABUF;
        const uint32_t bB = bBase + (uint32_t)buf * BBUF;
#pragma unroll
        for (int ks = 0; ks < 2; ks++) {
            uint32_t af[2][4];
#pragma unroll
            for (int mi = 0; mi < 2; mi++) {
                uint32_t addr = aB + (uint32_t)(mi * 16 * 80 + ks * 32);
                asm volatile(
                    "ldmatrix.sync.aligned.m8n8.x4.shared.b16 {%0,%1,%2,%3}, [%4];"
                    : "=r"(af[mi][0]), "=r"(af[mi][1]), "=r"(af[mi][2]), "=r"(af[mi][3])
                    : "r"(addr));
            }
            uint32_t bf[8][2];
#pragma unroll
            for (int g = 0; g < 4; g++) {
                uint32_t addr = bB + (uint32_t)(ks * 16 * 272 + g * 32);
                asm volatile(
                    "ldmatrix.sync.aligned.m8n8.x4.trans.shared.b16 {%0,%1,%2,%3}, [%4];"
                    : "=r"(bf[2 * g][0]), "=r"(bf[2 * g][1]),
                      "=r"(bf[2 * g + 1][0]), "=r"(bf[2 * g + 1][1])
                    : "r"(addr));
            }
#pragma unroll
            for (int mi = 0; mi < 2; mi++)
#pragma unroll
                for (int ni = 0; ni < 8; ni++) {
                    asm volatile(
                        "mma.sync.aligned.m16n8k16.row.col.f32.f16.f16.f32 "
                        "{%0,%1,%2,%3}, {%4,%5,%6,%7}, {%8,%9}, {%0,%1,%2,%3};"
                        : "+f"(acc[mi][ni][0]), "+f"(acc[mi][ni][1]),
                          "+f"(acc[mi][ni][2]), "+f"(acc[mi][ni][3])
                        : "r"(af[mi][0]), "r"(af[mi][1]), "r"(af[mi][2]), "r"(af[mi][3]),
                          "r"(bf[ni][0]), "r"(bf[ni][1]));
                }
        }

        if (it + 2 < nit) {
            int is = buf + 2; if (is >= STAGES) is -= STAGES;
            const int k0 = (it + 2) * BK;
            const uint32_t aD = aSt + (uint32_t)is * ABUF;
            const uint32_t bD = bSt + (uint32_t)is * BBUF;
#pragma unroll
            for (int i = 0; i < 2; i++)
                CP_ASYNC16(aD + (uint32_t)(i * 64 * 80),
                           &Sb[(size_t)(m0 + a_row0 + i * 64) * L + k0 + a_c8 * 8]);
#pragma unroll
            for (int i = 0; i < 2; i++)
                CP_ASYNC16(bD + (uint32_t)(i * 16 * 272),
                           &Eb[(size_t)posS[k0 + b_kr0 + i * 16] * K + b_n8 * 8]);
            CP_COMMIT();
            CP_WAIT1();
        } else if (it + 1 < nit) {
            CP_WAIT0();
        }
        __syncthreads();
        if (++buf == STAGES) buf = 0;
    }

    // Epilogue
#pragma unroll
    for (int mi = 0; mi < 2; mi++) {
#pragma unroll
        for (int ni = 0; ni < 8; ni++) {
            int gn = n0 + warp_n + ni * 8 + 2 * lr;
            int gm0 = m0 + warp_m + mi * 16 + lq;
            if (gm0 < R) {
                float2 v = make_float2(acc[mi][ni][0], acc[mi][ni][1]);
                *(float2*)&Ob[(size_t)gm0 * K + gn] = v;
            }
            int gm1 = gm0 + 8;
            if (gm1 < R) {
                float2 v = make_float2(acc[mi][ni][2], acc[mi][ni][3]);
                *(float2*)&Ob[(size_t)gm1 * K + gn] = v;
            }
        }
    }
}

// ---------------------------------------------------------------------------
extern "C" void kernel_launch(void* const* d_in, const int* in_sizes, int n_in,
                              void* d_out, int out_size) {
    const float* image_emb = (const float*)d_in[0]; // [B,R,L]
    const float* seq_emb   = (const float*)d_in[1]; // [B,L,K]
    const int*   mask      = (const int*)d_in[2];   // [B,L]
    const float* image_W   = (const float*)d_in[3]; // [L,1]
    const float* image_b   = (const float*)d_in[4]; // [1]
    const float* seq_W     = (const float*)d_in[5]; // [K,1]
    const float* seq_b     = (const float*)d_in[6]; // [1]
    const float* V_weight  = (const float*)d_in[7]; // [L,L]
    float* out = (float*)d_out;                     // [B,R,K]

    cudaFuncSetAttribute(k_gemm_f16, cudaFuncAttributeMaxDynamicSharedMemorySize,
                         SMEM_GEMM);

    k_prep1<<<(B * R + B * L) / 8, 256>>>(image_emb, image_W, image_b,
                                          seq_emb, seq_W, seq_b, mask);
    k_prep2<<<B, 512>>>(mask, V_weight);
    k_gemm_f16<<<dim3(K / BN, (R + BM - 1) / BM, B), 256, SMEM_GEMM>>>(out);
}